// round 7
// baseline (speedup 1.0000x reference)
#include <cuda_runtime.h>
#include <cuda_bf16.h>
#include <math.h>
#include <stdint.h>

// Problem constants
#define Bn 512
#define En 512
#define Cn 100000
#define NTILES 782            // ceil(100000/128)
#define S_SCALE 30.0f
#define SM_MARGIN 10.5f       // S*M = 30*0.35
#define LAMDA 0.01f
#define ALPHA_C 0.5f
#define EPS_C 1e-6f

#define LPAD 132              // logit smem row stride (floats)
#define SMEM_DYN (128 * LPAD * 4)   // 67584 bytes

// ------------------------- device scratch (static, no allocation) ----------
__device__ int              g_lab[Bn];
__device__ float            g_inv_e[Bn];
__device__ __nv_bfloat16    g_emb_bf[Bn * En];
__device__ float            g_inv_w[Cn];
__device__ __nv_bfloat16    g_w_bf[(size_t)Cn * En];
__device__ float            g_tgt[Bn];
__device__ float            g_pmax[(size_t)Bn * NTILES];
__device__ float            g_psum[(size_t)Bn * NTILES];
__device__ float            g_pamv[(size_t)Bn * NTILES];
__device__ int              g_pami[(size_t)Bn * NTILES];
__device__ float            g_rowloss[Bn];
__device__ int              g_correct[Bn];
__device__ float            g_closs;
__device__ float            g_appear[Bn];

__device__ __forceinline__ float neg_inf() { return __int_as_float(0xff800000); }

__device__ __forceinline__ void comb_ms(float& m, float& s, float m2, float s2) {
    if (m2 == neg_inf()) return;
    if (m2 > m) { s = s * __expf(m - m2) + s2; m = m2; }
    else        { s += s2 * __expf(m2 - m); }
}

// ------------------------- K-1: decode labels (int32 vs int64 autodetect) --
// JAX with x64 disabled silently downcasts jnp.int64 -> int32; handle both.
// Test: interpret the first 2048 bytes (= guaranteed-valid region in either
// layout) as 256 int64s. If ALL are in [0, Cn), layout is int64; otherwise
// it is int32. Never reads beyond the smaller buffer during detection.
__global__ void decode_labels_k(const void* __restrict__ labraw) {
    const long long* l64 = (const long long*)labraw;
    const int*       l32 = (const int*)labraw;
    int t = threadIdx.x;               // 256 threads
    long long v = l64[t];              // within first 2048 bytes: always safe
    int valid = (v >= 0 && v < (long long)Cn) ? 1 : 0;
    #pragma unroll
    for (int o = 16; o; o >>= 1) valid &= __shfl_xor_sync(0xffffffffu, valid, o);
    __shared__ int sv[8];
    if ((t & 31) == 0) sv[t >> 5] = valid;
    __syncthreads();
    int all64 = sv[0] & sv[1] & sv[2] & sv[3] & sv[4] & sv[5] & sv[6] & sv[7];
    if (all64) {                       // true int64 buffer (4096 bytes)
        g_lab[t]       = (int)l64[t];
        g_lab[t + 256] = (int)l64[t + 256];
    } else {                           // int32 buffer (2048 bytes)
        g_lab[t]       = l32[t];
        g_lab[t + 256] = l32[t + 256];
    }
}

// ------------------------- K0: embedding norms + bf16 ----------------------
__global__ void prep_emb_k(const float* __restrict__ emb) {
    int b = blockIdx.x;            // 512 blocks
    int t = threadIdx.x;           // 128 threads
    float4 v = reinterpret_cast<const float4*>(emb + (size_t)b * En)[t];
    float ss = v.x * v.x + v.y * v.y + v.z * v.z + v.w * v.w;
    #pragma unroll
    for (int o = 16; o; o >>= 1) ss += __shfl_xor_sync(0xffffffffu, ss, o);
    __shared__ float sp[4];
    if ((t & 31) == 0) sp[t >> 5] = ss;
    __syncthreads();
    if (t == 0) {
        g_inv_e[b] = rsqrtf(sp[0] + sp[1] + sp[2] + sp[3]);
        if (b == 0) g_closs = 0.0f;
    }
    __nv_bfloat162* dst = reinterpret_cast<__nv_bfloat162*>(g_emb_bf + (size_t)b * En);
    dst[t * 2]     = __floats2bfloat162_rn(v.x, v.y);
    dst[t * 2 + 1] = __floats2bfloat162_rn(v.z, v.w);
}

// ------------------------- K0b: appear counts ------------------------------
__global__ void appear_k() {
    __shared__ int labs[Bn];
    int t = threadIdx.x;
    labs[t] = g_lab[t];
    __syncthreads();
    int mine = labs[t], cnt = 0;
    #pragma unroll 8
    for (int i = 0; i < Bn; i++) cnt += (labs[i] == mine);
    g_appear[t] = (float)cnt;
}

// ------------------------- K1: weight norms + bf16 (warp per row) ----------
__global__ __launch_bounds__(256) void prep_w_k(const float* __restrict__ w) {
    int warp = threadIdx.x >> 5, lane = threadIdx.x & 31;
    int r = blockIdx.x * 8 + warp;          // 12500*8 = 100000 exactly
    const float4* src = reinterpret_cast<const float4*>(w + (size_t)r * En);
    float4 v[4];
    float ss = 0.f;
    #pragma unroll
    for (int p = 0; p < 4; p++) {
        v[p] = src[lane + p * 32];
        ss += v[p].x * v[p].x + v[p].y * v[p].y + v[p].z * v[p].z + v[p].w * v[p].w;
    }
    #pragma unroll
    for (int o = 16; o; o >>= 1) ss += __shfl_xor_sync(0xffffffffu, ss, o);
    if (lane == 0) g_inv_w[r] = rsqrtf(ss);
    __nv_bfloat162* dst = reinterpret_cast<__nv_bfloat162*>(g_w_bf + (size_t)r * En);
    #pragma unroll
    for (int p = 0; p < 4; p++) {
        dst[(lane + p * 32) * 2]     = __floats2bfloat162_rn(v[p].x, v[p].y);
        dst[(lane + p * 32) * 2 + 1] = __floats2bfloat162_rn(v[p].z, v[p].w);
    }
}

// ------------------------- K1b: exact fp32 target logit --------------------
__global__ __launch_bounds__(256) void tgt_k(const float* __restrict__ emb,
                                             const float* __restrict__ w) {
    int warp = threadIdx.x >> 5, lane = threadIdx.x & 31;
    int b = blockIdx.x * 8 + warp;          // 64*8 = 512
    int lab = g_lab[b];
    const float4* e4 = reinterpret_cast<const float4*>(emb + (size_t)b * En);
    const float4* w4 = reinterpret_cast<const float4*>(w + (size_t)lab * En);
    float dot = 0.f;
    #pragma unroll
    for (int p = 0; p < 4; p++) {
        float4 a = e4[lane + p * 32];
        float4 c = w4[lane + p * 32];
        dot += a.x * c.x + a.y * c.y + a.z * c.z + a.w * c.w;
    }
    #pragma unroll
    for (int o = 16; o; o >>= 1) dot += __shfl_xor_sync(0xffffffffu, dot, o);
    if (lane == 0)
        g_tgt[b] = S_SCALE * dot * g_inv_e[b] * g_inv_w[lab] - SM_MARGIN;
}

// ------------------------- K2: bf16 GEMM + fused online softmax ------------
__device__ __forceinline__ void mma16816(float* d, const uint32_t* a, const uint32_t* b) {
    asm volatile(
        "mma.sync.aligned.m16n8k16.row.col.f32.bf16.bf16.f32 "
        "{%0,%1,%2,%3}, {%4,%5,%6,%7}, {%8,%9}, {%0,%1,%2,%3};\n"
        : "+f"(d[0]), "+f"(d[1]), "+f"(d[2]), "+f"(d[3])
        : "r"(a[0]), "r"(a[1]), "r"(a[2]), "r"(a[3]), "r"(b[0]), "r"(b[1]));
}

// grid = (4, NTILES): x = m-tile (4 consecutive blocks share one B n-tile via L2)
__global__ __launch_bounds__(256, 2) void gemm_softmax_k() {
    extern __shared__ __align__(16) char dyn[];
    __nv_bfloat16* As = reinterpret_cast<__nv_bfloat16*>(dyn);            // [2][128][40]
    __nv_bfloat16* Bs = reinterpret_cast<__nv_bfloat16*>(dyn + 20480);    // [2][128][40]
    float*         Ls = reinterpret_cast<float*>(dyn);                    // [128][LPAD] (reused)

    const int tid  = threadIdx.x;
    const int warp = tid >> 5, lane = tid & 31;
    const int wm = warp & 1, wn = warp >> 1;       // warps: 2 (M) x 4 (N)
    const int gid = lane >> 2, t4 = lane & 3;
    const int m0 = blockIdx.x * 128, n0 = blockIdx.y * 128;

    __shared__ int   s_lab[128];
    __shared__ float s_inve[128], s_invw[128];

    if (tid < 128) {
        s_lab[tid]  = g_lab[m0 + tid];
        s_inve[tid] = g_inv_e[m0 + tid];
        int c = n0 + tid;
        s_invw[tid] = (c < Cn) ? g_inv_w[c] : 0.f;
    }

    float acc[4][4][4];
    #pragma unroll
    for (int a = 0; a < 4; a++)
        #pragma unroll
        for (int b = 0; b < 4; b++)
            #pragma unroll
            for (int c = 0; c < 4; c++) acc[a][b][c] = 0.f;

    auto load_stage = [&](int st, int kb) {
        #pragma unroll
        for (int i = 0; i < 2; i++) {
            int id  = tid + i * 256;
            int row = id >> 2, seg = id & 3;
            {   // A tile (embedding bf16)
                uint32_t dst = (uint32_t)__cvta_generic_to_shared(&As[(st * 128 + row) * 40 + seg * 8]);
                const void* src = &g_emb_bf[(size_t)(m0 + row) * En + kb + seg * 8];
                asm volatile("cp.async.cg.shared.global [%0], [%1], 16;\n" :: "r"(dst), "l"(src));
            }
            {   // B tile (weights bf16), zero-fill OOB rows
                int gn = n0 + row;
                uint32_t dst = (uint32_t)__cvta_generic_to_shared(&Bs[(st * 128 + row) * 40 + seg * 8]);
                size_t gnc = (gn < Cn) ? (size_t)gn : (size_t)(Cn - 1);
                const void* src = &g_w_bf[gnc * En + kb + seg * 8];
                int sz = (gn < Cn) ? 16 : 0;
                asm volatile("cp.async.cg.shared.global [%0], [%1], 16, %2;\n"
                             :: "r"(dst), "l"(src), "r"(sz));
            }
        }
        asm volatile("cp.async.commit_group;\n");
    };

    // Safe 2-stage pipeline: a stage is only overwritten AFTER the barrier
    // that retires all reads of it.
    load_stage(0, 0);
    load_stage(1, 32);
    #pragma unroll 1
    for (int ks = 0; ks < 16; ks++) {
        int st = ks & 1;
        if (ks < 15) asm volatile("cp.async.wait_group 1;\n");
        else         asm volatile("cp.async.wait_group 0;\n");
        __syncthreads();
        #pragma unroll
        for (int kk = 0; kk < 32; kk += 16) {
            uint32_t afr[4][4], bfr[4][2];
            #pragma unroll
            for (int mt = 0; mt < 4; mt++) {
                int r = wm * 64 + mt * 16 + gid;
                afr[mt][0] = *(const uint32_t*)&As[(st * 128 + r) * 40 + kk + t4 * 2];
                afr[mt][1] = *(const uint32_t*)&As[(st * 128 + r + 8) * 40 + kk + t4 * 2];
                afr[mt][2] = *(const uint32_t*)&As[(st * 128 + r) * 40 + kk + t4 * 2 + 8];
                afr[mt][3] = *(const uint32_t*)&As[(st * 128 + r + 8) * 40 + kk + t4 * 2 + 8];
            }
            #pragma unroll
            for (int nt = 0; nt < 4; nt++) {
                int c = wn * 32 + nt * 8 + gid;
                bfr[nt][0] = *(const uint32_t*)&Bs[(st * 128 + c) * 40 + kk + t4 * 2];
                bfr[nt][1] = *(const uint32_t*)&Bs[(st * 128 + c) * 40 + kk + t4 * 2 + 8];
            }
            #pragma unroll
            for (int mt = 0; mt < 4; mt++)
                #pragma unroll
                for (int nt = 0; nt < 4; nt++)
                    mma16816(acc[mt][nt], afr[mt], bfr[nt]);
        }
        __syncthreads();                       // retire all reads of stage st
        if (ks + 2 < 16) load_stage(st, (ks + 2) * 32);
    }

    // -------- epilogue A: stage scaled + margined logits to SMEM -----------
    #pragma unroll
    for (int mt = 0; mt < 4; mt++) {
        #pragma unroll
        for (int h = 0; h < 2; h++) {
            int row = wm * 64 + mt * 16 + gid + h * 8;
            int lab = s_lab[row];
            float sc = S_SCALE * s_inve[row];
            #pragma unroll
            for (int nt = 0; nt < 4; nt++) {
                #pragma unroll
                for (int j = 0; j < 2; j++) {
                    int col = wn * 32 + nt * 8 + t4 * 2 + j;
                    int cg = n0 + col;
                    float l = neg_inf();
                    if (cg < Cn) {
                        l = acc[mt][nt][h * 2 + j] * sc * s_invw[col];
                        if (cg == lab) l -= SM_MARGIN;
                    }
                    Ls[row * LPAD + col] = l;
                }
            }
        }
    }
    __syncthreads();

    // -------- epilogue B: serial reduce (2 threads per row) ----------------
    {
        int row = tid >> 1, half = tid & 1;
        const float* lp = Ls + row * LPAD + half * 64;
        float m = neg_inf(), s = 0.f, av = neg_inf();
        int ai = 0x7fffffff;
        int cbase = n0 + half * 64;
        #pragma unroll 4
        for (int c = 0; c < 64; c++) {
            float l = lp[c];
            if (l == neg_inf()) continue;     // OOB columns only
            if (l > av) { av = l; ai = cbase + c; }
            if (l > m) { s = s * __expf(m - l) + 1.f; m = l; }
            else       { s += __expf(l - m); }
        }
        float m2 = __shfl_xor_sync(0xffffffffu, m, 1);
        float s2 = __shfl_xor_sync(0xffffffffu, s, 1);
        comb_ms(m, s, m2, s2);
        float v2 = __shfl_xor_sync(0xffffffffu, av, 1);
        int   i2 = __shfl_xor_sync(0xffffffffu, ai, 1);
        if (v2 > av || (v2 == av && i2 < ai)) { av = v2; ai = i2; }
        if (half == 0) {
            size_t o = (size_t)(m0 + row) * NTILES + blockIdx.y;
            g_pmax[o] = m; g_psum[o] = s; g_pamv[o] = av; g_pami[o] = ai;
        }
    }
}

// ------------------------- K3: per-row LSE + argmax reduce -----------------
__global__ void reduce_rows_k() {
    int gw = (blockIdx.x * blockDim.x + threadIdx.x) >> 5;  // warp per row
    int lane = threadIdx.x & 31;
    if (gw >= Bn) return;
    float m = neg_inf(), s = 0.f, av = neg_inf();
    int ai = 0x7fffffff;
    const float* pm = g_pmax + (size_t)gw * NTILES;
    const float* ps = g_psum + (size_t)gw * NTILES;
    const float* pv = g_pamv + (size_t)gw * NTILES;
    const int*   pi = g_pami + (size_t)gw * NTILES;
    for (int t = lane; t < NTILES; t += 32) {
        comb_ms(m, s, pm[t], ps[t]);
        float v = pv[t]; int i = pi[t];
        if (v > av || (v == av && i < ai)) { av = v; ai = i; }
    }
    #pragma unroll
    for (int o = 16; o; o >>= 1) {
        float m2 = __shfl_xor_sync(0xffffffffu, m, o);
        float s2 = __shfl_xor_sync(0xffffffffu, s, o);
        comb_ms(m, s, m2, s2);
        float v2 = __shfl_xor_sync(0xffffffffu, av, o);
        int   i2 = __shfl_xor_sync(0xffffffffu, ai, o);
        if (v2 > av || (v2 == av && i2 < ai)) { av = v2; ai = i2; }
    }
    if (lane == 0) {
        float lse = m + logf(s);
        g_rowloss[gw] = lse - g_tgt[gw];
        g_correct[gw] = (ai == g_lab[gw]) ? 1 : 0;
    }
}

// ------------------------- K4: center loss ---------------------------------
__global__ void center_loss_k(const float* __restrict__ emb,
                              const float* __restrict__ centers) {
    int b = blockIdx.x;
    int r = g_lab[b];
    const float* e = emb + (size_t)b * En;
    const float* c = centers + (size_t)r * En;
    float ss = 0.f;
    for (int i = threadIdx.x; i < En; i += 256) {
        float d = e[i] - c[i];
        ss += d * d;
    }
    #pragma unroll
    for (int o = 16; o; o >>= 1) ss += __shfl_xor_sync(0xffffffffu, ss, o);
    __shared__ float sp[8];
    int warp = threadIdx.x >> 5, lane = threadIdx.x & 31;
    if (lane == 0) sp[warp] = ss;
    __syncthreads();
    if (threadIdx.x == 0) {
        float t = 0.f;
        #pragma unroll
        for (int i = 0; i < 8; i++) t += sp[i];
        atomicAdd(&g_closs, t);
    }
}

// ------------------------- K5: copy centers -> out -------------------------
__global__ void copy_centers_k(const float* __restrict__ centers, float* __restrict__ out) {
    size_t i = (size_t)blockIdx.x * blockDim.x + threadIdx.x;   // float2 index
    const float2* src = reinterpret_cast<const float2*>(centers);
    float2* dst = reinterpret_cast<float2*>(out);
    dst[i] = src[i];
}

// ------------------------- K6: scatter center update -----------------------
__global__ void scatter_k(const float* __restrict__ emb,
                          const float* __restrict__ centers,
                          float* __restrict__ outc) {
    int b = blockIdx.x;
    int r = g_lab[b];
    float coef = ALPHA_C / (g_appear[b] + EPS_C);
    const float* e = emb + (size_t)b * En;
    const float* c = centers + (size_t)r * En;
    float* o = outc + (size_t)r * En;
    for (int i = threadIdx.x; i < En; i += 128)
        atomicAdd(&o[i], coef * (e[i] - c[i]));
}

// ------------------------- K7: finalize scalars ----------------------------
__global__ void finalize_k(float* __restrict__ out) {
    int tid = threadIdx.x;  // 512
    float sl = g_rowloss[tid];
    int   sc = g_correct[tid];
    #pragma unroll
    for (int o = 16; o; o >>= 1) {
        sl += __shfl_xor_sync(0xffffffffu, sl, o);
        sc += __shfl_xor_sync(0xffffffffu, sc, o);
    }
    __shared__ float sm_l[16];
    __shared__ int   sm_c[16];
    if ((tid & 31) == 0) { sm_l[tid >> 5] = sl; sm_c[tid >> 5] = sc; }
    __syncthreads();
    if (tid == 0) {
        float L = 0.f; int Cc = 0;
        #pragma unroll
        for (int i = 0; i < 16; i++) { L += sm_l[i]; Cc += sm_c[i]; }
        out[0] = 100.0f * (float)Cc / (float)Bn;
        out[1] = L / (float)Bn + LAMDA * (g_closs / (float)(Bn * En));
    }
}

// ------------------------- launcher ---------------------------------------
extern "C" void kernel_launch(void* const* d_in, const int* in_sizes, int n_in,
                              void* d_out, int out_size) {
    (void)in_sizes; (void)n_in; (void)out_size;
    const float* emb = (const float*)d_in[0];
    const float* w   = (const float*)d_in[1];
    const float* cen = (const float*)d_in[2];
    const void*  lab = d_in[3];
    float* out = (float*)d_out;

    cudaFuncSetAttribute(gemm_softmax_k,
                         cudaFuncAttributeMaxDynamicSharedMemorySize, SMEM_DYN);

    decode_labels_k<<<1, 256>>>(lab);
    prep_emb_k<<<Bn, 128>>>(emb);
    appear_k<<<1, Bn>>>();
    prep_w_k<<<Cn / 8, 256>>>(w);
    tgt_k<<<Bn / 8, 256>>>(emb, w);
    copy_centers_k<<<100000, 256>>>(cen, out + 2);
    gemm_softmax_k<<<dim3(4, NTILES), 256, SMEM_DYN>>>();
    reduce_rows_k<<<64, 256>>>();
    center_loss_k<<<Bn, 256>>>(emb, cen);
    scatter_k<<<Bn, 128>>>(emb, cen, out + 2);
    finalize_k<<<1, Bn>>>(out);
}